// round 11
// baseline (speedup 1.0000x reference)
#include <cuda_runtime.h>

#define THREADS 512
#define BINS 256
#define NBLOCKS (148 * 4)       // 4 blocks/SM x 512 threads = 2048 threads/SM
#define VPT 3                   // float4 per thread per tile (MLP_p1=3, proven R8)
#define TILE_V (THREADS * VPT)  // 1536 float4 = 24KB per tile

// Zero-initialized device scratch. The last block re-zeroes everything each
// call, so every graph replay sees identical initial state. Tile->block
// assignment is nondeterministic but integer-count summation is
// order-independent -> bit-identical output every run.
__device__ unsigned int g_partial[BINS];
__device__ unsigned int g_ticket;
__device__ unsigned int g_tile;

// Histogram layout h[bin][lane]: lane l only touches column l -> every
// warp-ATOMS hits 32 DISTINCT banks. Structurally conflict-free shared
// atomics (proven R7: L1% 63->33, dur 51.7->47.2).
__device__ __forceinline__ void bin_one(float f, unsigned int* hl) {
    // torch.histc: bins over [-4,4], x==4 -> last bin, outside ignored.
    // (f+4)*32 == fmaf(f,32,128) bit-exactly (x32 is an exact binade shift).
    if (fabsf(f) <= 4.0f) {
        int b = __float2int_rd(fmaf(f, 32.0f, 128.0f));
        b = min(b, BINS - 1);
        atomicAdd(&hl[b << 5], 1u);   // hl already offset by lane
    }
}

__device__ __forceinline__ void bin4(float4 v, unsigned int* hl) {
    bin_one(v.x, hl);
    bin_one(v.y, hl);
    bin_one(v.z, hl);
    bin_one(v.w, hl);
}

__global__ __launch_bounds__(THREADS) void histc_kernel(
    const float4* __restrict__ x, float* __restrict__ out, int n4, int dup)
{
    __shared__ unsigned int h[BINS * 32];   // 32 KB: h[b*32 + lane]
    __shared__ unsigned int s_tile[2];      // double-buffered ticket slots
    __shared__ bool is_last;

    #pragma unroll
    for (int i = threadIdx.x; i < BINS * 32; i += THREADS)
        h[i] = 0u;

    const int lane = threadIdx.x & 31;
    unsigned int* hl = &h[lane];
    const unsigned int ntiles = (unsigned int)((n4 + TILE_V - 1) / TILE_V);

    // Dynamic tile scheduler: fast SMs take more tiles, erasing between-SM
    // spread (L2-die variance floor ~1.10x on static partitions). Tickets are
    // double-buffered so only ONE barrier per tile is needed: thread 0
    // fetches ticket p+1 into the other slot while the block bins ticket p.
    if (threadIdx.x == 0)
        s_tile[0] = atomicAdd(&g_tile, 1u);
    __syncthreads();                         // covers h[] zeroing + slot 0

    unsigned int p = 0;
    for (;;) {
        unsigned int t = s_tile[p & 1];      // uniform across block
        if (t >= ntiles)
            break;
        if (threadIdx.x == 0)
            s_tile[(p + 1) & 1] = atomicAdd(&g_tile, 1u);  // prefetch next;
                                             // ATOMG latency hides under work
        int base = (int)t * TILE_V + threadIdx.x;
        if ((int)(t + 1) * TILE_V <= n4) {
            // Full tile: 3 front-batched 16B streaming loads (MLP_p1=3).
            float4 a = __ldcs(&x[base]);
            float4 b = __ldcs(&x[base + THREADS]);
            float4 c = __ldcs(&x[base + 2 * THREADS]);
            bin4(a, hl);
            bin4(b, hl);
            bin4(c, hl);
        } else {
            for (int i = base; i < n4; i += THREADS)
                bin4(__ldcs(&x[i]), hl);
        }
        __syncthreads();                     // publish next ticket slot
        p++;
    }
    __syncthreads();

    // Reduce 32 lane-columns per bin. Diagonal read (start at own lane) keeps
    // all 32 lanes of a warp on distinct banks every step.
    if (threadIdx.x < BINS) {
        int b = threadIdx.x;
        unsigned int s = 0;
        #pragma unroll
        for (int k = 0; k < 32; k++)
            s += h[(b << 5) + ((k + lane) & 31)];
        if (s)
            atomicAdd(&g_partial[b], s);
    }

    // Last-block-done epilogue: final block writes both output copies and
    // resets all scratch. Plain stores overwrite the harness poison.
    __threadfence();
    if (threadIdx.x == 0) {
        unsigned int tk = atomicAdd(&g_ticket, 1u);
        is_last = (tk == (unsigned int)gridDim.x - 1u);
    }
    __syncthreads();

    if (is_last && threadIdx.x < BINS) {
        int b = threadIdx.x;
        unsigned int v = atomicAdd(&g_partial[b], 0u);  // L2-coherent read
        float fv = (float)v;
        out[b] = fv;
        if (dup)
            out[b + BINS] = fv;
        g_partial[b] = 0u;      // reset scratch for next graph replay
        if (b == 0) {
            g_ticket = 0u;
            g_tile = 0u;
        }
    }
}

extern "C" void kernel_launch(void* const* d_in, const int* in_sizes, int n_in,
                              void* d_out, int out_size)
{
    const float4* x = (const float4*)d_in[0];
    float* out = (float*)d_out;
    int n4 = in_sizes[0] / 4;
    int dup = (out_size >= 2 * BINS) ? 1 : 0;

    histc_kernel<<<NBLOCKS, THREADS>>>(x, out, n4, dup);
}